// round 8
// baseline (speedup 1.0000x reference)
#include <cuda_runtime.h>
#include <cuda_fp16.h>
#include <cstddef>

#define EPSF 1e-6f
#define LAMBDAF 0.01f

// Problem constants (fixed shapes)
//  x: (4,16,16,16,16)  a: (4,16,16,16,1)  w: (144,32,4,4)
//  out: p_out (4,14,14,32,16) ++ a_out (4,14,14,32,1)
#define NCAP 144
#define CCAP 32
#define NPOS 784           // 4*14*14
#define POUT_ELEMS 401408  // 784*32*16
#define WHALF_ELEMS (NCAP * CCAP * 16)  // 73728 halves = 144KB (L1-resident)

// fp16 weight staging buffer, layout [n][k2][c][8]:
//   wh[((n*2+k2)*32 + c)*8 + j] = w[n][c][ k2*8 + j ]
__device__ __half g_wh[WHALF_ELEMS];

// One thread produces one uint4 (8 halves) from two float4 loads.
__global__ void convert_w_kernel(const float* __restrict__ w) {
    int q = blockIdx.x * 256 + threadIdx.x;  // 0..9215
    if (q >= WHALF_ELEMS / 8) return;
    int c = q & 31;
    int k2 = (q >> 5) & 1;
    int n = q >> 6;
    const float4* src = reinterpret_cast<const float4*>(w + ((n * 32 + c) << 4) + k2 * 8);
    float4 f0 = __ldg(src + 0), f1 = __ldg(src + 1);
    __half2 h[4];
    h[0] = __floats2half2_rn(f0.x, f0.y);
    h[1] = __floats2half2_rn(f0.z, f0.w);
    h[2] = __floats2half2_rn(f1.x, f1.y);
    h[3] = __floats2half2_rn(f1.z, f1.w);
    reinterpret_cast<uint4*>(g_wh)[q] = *reinterpret_cast<uint4*>(h);
}

__device__ __forceinline__ float warp_max(float v) {
#pragma unroll
    for (int o = 16; o; o >>= 1) v = fmaxf(v, __shfl_xor_sync(0xffffffffu, v, o));
    return v;
}

struct Smem {
    float pose[2304];   // [n*16 + p], pose patch
    float a[144];       // a_in per n
    float WS[8 * 548];  // per-warp reduction staging (stride-17 padded)
    float M1[544];      // S1 (sum r*v) then mu, in place  [c*17+p]
    float M2[544];      // I2S = 1/(2 sigma^2)             [c*17+p]
    float RSB[8 * 33];  // per-warp rsum staging
    float RS[32];       // r_sum per c
    float SH[32];       // sum_p 0.5*log(sigma^2) per c
    float Lc[32];       // log(a_out+eps) - SH[c]
    float AO[32];       // a_out per c
};

// Compute 16 votes for capsule n (weights fp16, L1-resident; pose smem bcast).
__device__ __forceinline__ void votes16(const Smem& sm, int n, int lane, float* v) {
    const uint4* whv = reinterpret_cast<const uint4*>(g_wh);
    uint4 ua = __ldg(whv + (n * 2 + 0) * 32 + lane);  // rows j=0,1
    uint4 ub = __ldg(whv + (n * 2 + 1) * 32 + lane);  // rows j=2,3
    const __half2* ha = reinterpret_cast<const __half2*>(&ua);
    const __half2* hb = reinterpret_cast<const __half2*>(&ub);
    float w0[4], w1[4], w2[4], w3[4];
    float2 t;
    t = __half22float2(ha[0]); w0[0] = t.x; w0[1] = t.y;
    t = __half22float2(ha[1]); w0[2] = t.x; w0[3] = t.y;
    t = __half22float2(ha[2]); w1[0] = t.x; w1[1] = t.y;
    t = __half22float2(ha[3]); w1[2] = t.x; w1[3] = t.y;
    t = __half22float2(hb[0]); w2[0] = t.x; w2[1] = t.y;
    t = __half22float2(hb[1]); w2[2] = t.x; w2[3] = t.y;
    t = __half22float2(hb[2]); w3[0] = t.x; w3[1] = t.y;
    t = __half22float2(hb[3]); w3[2] = t.x; w3[3] = t.y;
    const float* ps = sm.pose + n * 16;
#pragma unroll
    for (int i = 0; i < 4; i++) {
        float p0 = ps[4 * i + 0], p1 = ps[4 * i + 1], p2 = ps[4 * i + 2], p3 = ps[4 * i + 3];
#pragma unroll
        for (int k = 0; k < 4; k++)
            v[4 * i + k] = fmaf(p0, w0[k], fmaf(p1, w1[k], fmaf(p2, w2[k], p3 * w3[k])));
    }
}

// Shared epilogue of a vote pass: stage + reduce T1/rsum into M1/RS, stage T2.
// (T2's reduction is merged into stats() to save one barrier.)
__device__ __forceinline__ void pass_reduce(Smem& sm, const float* T1, const float* T2,
                                            float rsum, int lane, int g, int tid) {
#pragma unroll
    for (int p = 0; p < 16; p++) sm.WS[g * 548 + lane * 17 + p] = T1[p];
    sm.RSB[g * 33 + lane] = rsum;
    __syncthreads();
    for (int q = tid; q < 512; q += 256) {
        int c = q >> 4, p = q & 15;
        float s = 0.f;
#pragma unroll
        for (int gg = 0; gg < 8; gg++) s += sm.WS[gg * 548 + c * 17 + p];
        sm.M1[c * 17 + p] = s;
    }
    if (tid < 32) {
        float s = 0.f;
#pragma unroll
        for (int gg = 0; gg < 8; gg++) s += sm.RSB[gg * 33 + tid];
        sm.RS[tid] = s;
    }
    __syncthreads();
#pragma unroll
    for (int p = 0; p < 16; p++) sm.WS[g * 548 + lane * 17 + p] = T2[p];
    __syncthreads();
}

// Pass 0: uniform responsibilities r0 = a_n / C.
__device__ __forceinline__ void vote_pass0(Smem& sm, int lane, int g, int tid) {
    float T1[16], T2[16];
#pragma unroll
    for (int p = 0; p < 16; p++) { T1[p] = 0.f; T2[p] = 0.f; }
    float rsum = 0.f;
#pragma unroll 3
    for (int n = g; n < NCAP; n += 8) {
        float v[16];
        votes16(sm, n, lane, v);
        float rn = sm.a[n] * (1.0f / 32.0f);
        rsum += rn;
#pragma unroll
        for (int p = 0; p < 16; p++) {
            float rv = rn * v[p];
            T1[p] += rv;
            T2[p] = fmaf(rv, v[p], T2[p]);
        }
    }
    pass_reduce(sm, T1, T2, rsum, lane, g, tid);
}

// E+M pass: fused E-step (warp softmax over c=lane, pass-constant shift folded
// into Lr) + next M accumulation. Two capsules (n, n+8) per step, shuffle
// chains interleaved; FULLY UNROLLED with a branchless underflow guard so
// ptxas can software-pipeline the next pair's votes into the shuffle shadow.
__device__ __forceinline__ void vote_passE(Smem& sm, int lane, int g, int tid) {
    float A[16], Bv[16];
    float C = 0.f;
#pragma unroll
    for (int p = 0; p < 16; p++) {
        float m_ = sm.M1[lane * 17 + p];
        float ii = sm.M2[lane * 17 + p];
        A[p] = ii;
        Bv[p] = -2.0f * ii * m_;
        C = fmaf(ii * m_, m_, C);
    }
    float Lr2 = sm.Lc[lane] - C;
    float Lrm = Lr2 - warp_max(Lr2);  // shift folded in: ln' = Lrm - ds  (<= 0)

    float T1[16], T2[16];
#pragma unroll
    for (int p = 0; p < 16; p++) { T1[p] = 0.f; T2[p] = 0.f; }
    float rsum = 0.f;

#pragma unroll
    for (int i = 0; i < 9; i++) {  // 9 pairs (n, n+8), fully unrolled
        int n = g + i * 16;
        float vA[16], vB[16];
        votes16(sm, n, lane, vA);
        float dsA = 0.f;
#pragma unroll
        for (int p = 0; p < 16; p++) {
            float t = fmaf(A[p], vA[p], Bv[p]);
            dsA = fmaf(t, vA[p], dsA);
        }
        float eA = __expf(Lrm - dsA);
        votes16(sm, n + 8, lane, vB);
        float dsB = 0.f;
#pragma unroll
        for (int p = 0; p < 16; p++) {
            float t = fmaf(A[p], vB[p], Bv[p]);
            dsB = fmaf(t, vB[p], dsB);
        }
        float eB = __expf(Lrm - dsB);
        // interleaved butterfly sums over the 32 lanes (softmax over c)
        float seA = eA, seB = eB;
#pragma unroll
        for (int o = 16; o; o >>= 1) {
            seA += __shfl_xor_sync(0xffffffffu, seA, o);
            seB += __shfl_xor_sync(0xffffffffu, seB, o);
        }
        // branchless guard (never binds on real data; keeps one basic block)
        seA = fmaxf(seA, 1e-30f);
        seB = fmaxf(seB, 1e-30f);
        float rnA = sm.a[n] * __fdividef(eA, seA);
        float rnB = sm.a[n + 8] * __fdividef(eB, seB);
        rsum += rnA + rnB;
#pragma unroll
        for (int p = 0; p < 16; p++) {
            float rvA = rnA * vA[p];
            float rvB = rnB * vB[p];
            T1[p] += rvA + rvB;
            T2[p] = fmaf(rvA, vA[p], fmaf(rvB, vB[p], T2[p]));
        }
    }
    pass_reduce(sm, T1, T2, rsum, lane, g, tid);
}

// M-step statistics. Phase 1 also finishes the T2 reduction (staged in WS) and
// computes sum_p 0.5*log(sigma^2) per c via 16-lane shuffles (no smem round-trip).
__device__ __forceinline__ void stats(Smem& sm, const float* __restrict__ bu,
                                      const float* __restrict__ ba, int tid) {
    for (int q = tid; q < 512; q += 256) {
        int c = q >> 4, p = q & 15, qi = c * 17 + p;
        float s2 = 0.f;
#pragma unroll
        for (int gg = 0; gg < 8; gg++) s2 += sm.WS[gg * 548 + c * 17 + p];
        float rs = sm.RS[c];
        float inv = __fdividef(1.0f, rs + EPSF);
        float mu = sm.M1[qi] * inv;
        // sigma^2 = S2/(rs+eps) - mu^2 * (2 - rs/(rs+eps)) + eps
        float sig = fmaf(-mu * mu, 2.0f - rs * inv, s2 * inv) + EPSF;
        sm.M1[qi] = mu;  // in place: S1 -> mu
        sm.M2[qi] = __fdividef(0.5f, sig);
        // sum of 0.5*log(sig) over the 16 lanes sharing this c (lane = c*16+p mod 32)
        float hl = 0.5f * __logf(sig);
#pragma unroll
        for (int o = 1; o < 16; o <<= 1) hl += __shfl_xor_sync(0xffffffffu, hl, o);
        if (p == 0) sm.SH[c] = hl;
    }
    __syncthreads();
    if (tid < 32) {
        int c = tid;
        float sumh = sm.SH[c];
        float cost = (16.0f * bu[c] + sumh) * sm.RS[c];
        float logit = LAMBDAF * (ba[c] - cost);
        float ao = __fdividef(1.0f, 1.0f + __expf(-logit));
        sm.AO[c] = ao;
        sm.Lc[c] = __logf(ao + EPSF) - sumh;
    }
    __syncthreads();
}

__global__ __launch_bounds__(256, 2) void convcaps_kernel(
    const float* __restrict__ x, const float* __restrict__ a,
    const float* __restrict__ bu, const float* __restrict__ ba,
    const int* __restrict__ itp, float* __restrict__ out) {
    __shared__ Smem sm;
    int tid = threadIdx.x, lane = tid & 31, g = tid >> 5;
    int pid = blockIdx.x;
    int b = pid / 196;
    int rem = pid - b * 196;
    int oy = rem / 14;
    int ox = rem - oy * 14;

    // Patch gather (float4-vectorized): n = (ki*3+kj)*16 + bc
    for (int q = tid; q < 576; q += 256) {
        int n = q >> 2, f = q & 3;
        int bc = n & 15, kk = n >> 4;
        int ki = kk / 3, kj = kk - ki * 3;
        const float4* src = reinterpret_cast<const float4*>(
            x + (((size_t)(b * 16 + oy + ki) * 16 + (ox + kj)) * 16 + bc) * 16);
        reinterpret_cast<float4*>(sm.pose)[q] = __ldg(src + f);
    }
    for (int n = tid; n < NCAP; n += 256) {
        int bc = n & 15, kk = n >> 4;
        int ki = kk / 3, kj = kk - ki * 3;
        sm.a[n] = a[((size_t)(b * 16 + oy + ki) * 16 + (ox + kj)) * 16 + bc];
    }
    __syncthreads();

    int iters = 2;
    if (itp) {
        int iv = __ldg(itp);
        if (iv >= 1 && iv <= 64) {
            iters = iv;
        } else {
            float f = __int_as_float(iv);  // guard against float-encoded scalar
            if (f >= 1.0f && f <= 64.0f) iters = (int)f;
        }
    }

    // iteration 0: uniform responsibilities
    vote_pass0(sm, lane, g, tid);
    stats(sm, bu, ba, tid);
    // iterations 1..iters-1: fused E-step (of prev iter) + M-accumulation
    for (int it = 1; it < iters; ++it) {
        vote_passE(sm, lane, g, tid);
        stats(sm, bu, ba, tid);
    }

    // outputs: p_out (pid*512 + c*16+p) then a_out (POUT_ELEMS + pid*32 + c)
    float* pout = out + (size_t)pid * 512;
    for (int q = tid; q < 512; q += 256) {
        int c = q >> 4, p = q & 15;
        pout[q] = sm.M1[c * 17 + p];
    }
    if (tid < 32) out[POUT_ELEMS + pid * 32 + tid] = sm.AO[tid];
}

extern "C" void kernel_launch(void* const* d_in, const int* in_sizes, int n_in,
                              void* d_out, int out_size) {
    const float* x = (const float*)d_in[0];
    const float* a = (const float*)d_in[1];
    const float* w = (const float*)d_in[2];
    const float* bu = (const float*)d_in[3];
    const float* ba = (const float*)d_in[4];
    const int* itp = (n_in >= 6) ? (const int*)d_in[5] : nullptr;
    convert_w_kernel<<<(WHALF_ELEMS / 8 + 255) / 256, 256>>>(w);
    convcaps_kernel<<<NPOS, 256>>>(x, a, bu, ba, itp, (float*)d_out);
}

// round 9
// speedup vs baseline: 1.5451x; 1.5451x over previous
#include <cuda_runtime.h>
#include <cuda_fp16.h>
#include <cstddef>

#define EPSF 1e-6f
#define LAMBDAF 0.01f

// Problem constants (fixed shapes)
//  x: (4,16,16,16,16)  a: (4,16,16,16,1)  w: (144,32,4,4)
//  out: p_out (4,14,14,32,16) ++ a_out (4,14,14,32,1)
#define NCAP 144
#define CCAP 32
#define NPOS 784           // 4*14*14
#define POUT_ELEMS 401408  // 784*32*16
#define WHALF_ELEMS (NCAP * CCAP * 16)  // 73728 halves = 144KB (L1-resident)

// fp16 weight staging buffer, layout [n][k2][c][8]:
//   wh[((n*2+k2)*32 + c)*8 + j] = w[n][c][ k2*8 + j ]
__device__ __half g_wh[WHALF_ELEMS];

// One thread produces one uint4 (8 halves) from two float4 loads.
__global__ void convert_w_kernel(const float* __restrict__ w) {
    int q = blockIdx.x * 256 + threadIdx.x;  // 0..9215
    if (q >= WHALF_ELEMS / 8) return;
    int c = q & 31;
    int k2 = (q >> 5) & 1;
    int n = q >> 6;
    const float4* src = reinterpret_cast<const float4*>(w + ((n * 32 + c) << 4) + k2 * 8);
    float4 f0 = __ldg(src + 0), f1 = __ldg(src + 1);
    __half2 h[4];
    h[0] = __floats2half2_rn(f0.x, f0.y);
    h[1] = __floats2half2_rn(f0.z, f0.w);
    h[2] = __floats2half2_rn(f1.x, f1.y);
    h[3] = __floats2half2_rn(f1.z, f1.w);
    reinterpret_cast<uint4*>(g_wh)[q] = *reinterpret_cast<uint4*>(h);
}

__device__ __forceinline__ float warp_max(float v) {
#pragma unroll
    for (int o = 16; o; o >>= 1) v = fmaxf(v, __shfl_xor_sync(0xffffffffu, v, o));
    return v;
}

struct Smem {
    float pose[2304];   // [n*16 + p], pose patch
    float a[144];       // a_in per n
    float WS[8 * 548];  // per-warp reduction staging (stride-17 padded)
    float M1[640];      // S1 (sum r*v) then mu, in place  [c*20+p] (float4-friendly pad)
    float M2[640];      // I2S = 1/(2 sigma^2)             [c*20+p]
    float BB[640];      // -2 * I2S * mu                   [c*20+p]
    float RSB[8 * 33];  // per-warp rsum staging
    float RS[32];       // r_sum per c
    float SH[32];       // sum_p 0.5*log(sigma^2) per c
    float CC[32];       // sum_p i2s*mu^2 per c
    float Lc[32];       // log(a_out+eps) - SH[c] - CC[c]
    float AO[32];       // a_out per c
};

// Compute 16 votes for capsule n (weights fp16, L1-resident; pose smem bcast).
__device__ __forceinline__ void votes16(const Smem& sm, int n, int lane, float* v) {
    const uint4* whv = reinterpret_cast<const uint4*>(g_wh);
    uint4 ua = __ldg(whv + (n * 2 + 0) * 32 + lane);  // rows j=0,1
    uint4 ub = __ldg(whv + (n * 2 + 1) * 32 + lane);  // rows j=2,3
    const __half2* ha = reinterpret_cast<const __half2*>(&ua);
    const __half2* hb = reinterpret_cast<const __half2*>(&ub);
    float w0[4], w1[4], w2[4], w3[4];
    float2 t;
    t = __half22float2(ha[0]); w0[0] = t.x; w0[1] = t.y;
    t = __half22float2(ha[1]); w0[2] = t.x; w0[3] = t.y;
    t = __half22float2(ha[2]); w1[0] = t.x; w1[1] = t.y;
    t = __half22float2(ha[3]); w1[2] = t.x; w1[3] = t.y;
    t = __half22float2(hb[0]); w2[0] = t.x; w2[1] = t.y;
    t = __half22float2(hb[1]); w2[2] = t.x; w2[3] = t.y;
    t = __half22float2(hb[2]); w3[0] = t.x; w3[1] = t.y;
    t = __half22float2(hb[3]); w3[2] = t.x; w3[3] = t.y;
    const float* ps = sm.pose + n * 16;
#pragma unroll
    for (int i = 0; i < 4; i++) {
        float p0 = ps[4 * i + 0], p1 = ps[4 * i + 1], p2 = ps[4 * i + 2], p3 = ps[4 * i + 3];
#pragma unroll
        for (int k = 0; k < 4; k++)
            v[4 * i + k] = fmaf(p0, w0[k], fmaf(p1, w1[k], fmaf(p2, w2[k], p3 * w3[k])));
    }
}

// Shared epilogue of a vote pass: stage + reduce T1/rsum into M1/RS, stage T2.
// (T2's reduction is merged into stats() to save one barrier.)
__device__ __forceinline__ void pass_reduce(Smem& sm, const float* T1, const float* T2,
                                            float rsum, int lane, int g, int tid) {
#pragma unroll
    for (int p = 0; p < 16; p++) sm.WS[g * 548 + lane * 17 + p] = T1[p];
    sm.RSB[g * 33 + lane] = rsum;
    __syncthreads();
    for (int q = tid; q < 512; q += 256) {
        int c = q >> 4, p = q & 15;
        float s = 0.f;
#pragma unroll
        for (int gg = 0; gg < 8; gg++) s += sm.WS[gg * 548 + c * 17 + p];
        sm.M1[c * 20 + p] = s;
    }
    if (tid < 32) {
        float s = 0.f;
#pragma unroll
        for (int gg = 0; gg < 8; gg++) s += sm.RSB[gg * 33 + tid];
        sm.RS[tid] = s;
    }
    __syncthreads();
#pragma unroll
    for (int p = 0; p < 16; p++) sm.WS[g * 548 + lane * 17 + p] = T2[p];
    __syncthreads();
}

// Pass 0: uniform responsibilities r0 = a_n / C.
__device__ __forceinline__ void vote_pass0(Smem& sm, int lane, int g, int tid) {
    float T1[16], T2[16];
#pragma unroll
    for (int p = 0; p < 16; p++) { T1[p] = 0.f; T2[p] = 0.f; }
    float rsum = 0.f;
#pragma unroll 2
    for (int n = g; n < NCAP; n += 8) {
        float v[16];
        votes16(sm, n, lane, v);
        float rn = sm.a[n] * (1.0f / 32.0f);
        rsum += rn;
#pragma unroll
        for (int p = 0; p < 16; p++) {
            float rv = rn * v[p];
            T1[p] += rv;
            T2[p] = fmaf(rv, v[p], T2[p]);
        }
    }
    pass_reduce(sm, T1, T2, rsum, lane, g, tid);
}

// E+M pass: fused E-step (warp softmax over c=lane) + next M accumulation.
// The Gaussian constants live in SMEM (A=M2, B=BB; C folded into Lc by stats),
// freeing ~32 registers so unroll-2 pipelining fits under the 128-reg cap.
__device__ __forceinline__ void vote_passE(Smem& sm, int lane, int g, int tid) {
    float Lrm;
    {
        float Lr2 = sm.Lc[lane];
        Lrm = Lr2 - warp_max(Lr2);  // shift folded in: ln' = Lrm - ds  (<= 0)
    }
    float T1[16], T2[16];
#pragma unroll
    for (int p = 0; p < 16; p++) { T1[p] = 0.f; T2[p] = 0.f; }
    float rsum = 0.f;

    const float4* A4p = reinterpret_cast<const float4*>(sm.M2 + lane * 20);
    const float4* B4p = reinterpret_cast<const float4*>(sm.BB + lane * 20);

#pragma unroll 2
    for (int n = g; n < NCAP; n += 16) {  // 9 pairs (n, n+8)
        float vA[16], vB[16];
        votes16(sm, n, lane, vA);
        votes16(sm, n + 8, lane, vB);
        float dsA = 0.f, dsB = 0.f;
#pragma unroll
        for (int i = 0; i < 4; i++) {
            float4 A4 = A4p[i];
            float4 B4 = B4p[i];
            float t;
            t = fmaf(A4.x, vA[4 * i + 0], B4.x); dsA = fmaf(t, vA[4 * i + 0], dsA);
            t = fmaf(A4.y, vA[4 * i + 1], B4.y); dsA = fmaf(t, vA[4 * i + 1], dsA);
            t = fmaf(A4.z, vA[4 * i + 2], B4.z); dsA = fmaf(t, vA[4 * i + 2], dsA);
            t = fmaf(A4.w, vA[4 * i + 3], B4.w); dsA = fmaf(t, vA[4 * i + 3], dsA);
            t = fmaf(A4.x, vB[4 * i + 0], B4.x); dsB = fmaf(t, vB[4 * i + 0], dsB);
            t = fmaf(A4.y, vB[4 * i + 1], B4.y); dsB = fmaf(t, vB[4 * i + 1], dsB);
            t = fmaf(A4.z, vB[4 * i + 2], B4.z); dsB = fmaf(t, vB[4 * i + 2], dsB);
            t = fmaf(A4.w, vB[4 * i + 3], B4.w); dsB = fmaf(t, vB[4 * i + 3], dsB);
        }
        float eA = __expf(Lrm - dsA);
        float eB = __expf(Lrm - dsB);
        // interleaved butterfly sums over the 32 lanes (softmax over c)
        float seA = eA, seB = eB;
#pragma unroll
        for (int o = 16; o; o >>= 1) {
            seA += __shfl_xor_sync(0xffffffffu, seA, o);
            seB += __shfl_xor_sync(0xffffffffu, seB, o);
        }
        // branchless guard (never binds on real data; keeps one basic block)
        seA = fmaxf(seA, 1e-30f);
        seB = fmaxf(seB, 1e-30f);
        float rnA = sm.a[n] * __fdividef(eA, seA);
        float rnB = sm.a[n + 8] * __fdividef(eB, seB);
        rsum += rnA + rnB;
#pragma unroll
        for (int p = 0; p < 16; p++) {
            float rvA = rnA * vA[p];
            float rvB = rnB * vB[p];
            T1[p] += rvA + rvB;
            T2[p] = fmaf(rvA, vA[p], fmaf(rvB, vB[p], T2[p]));
        }
    }
    pass_reduce(sm, T1, T2, rsum, lane, g, tid);
}

// M-step statistics. Finishes the T2 reduction (staged in WS), writes mu/I2S/BB,
// and reduces both 0.5*log(sigma^2) and i2s*mu^2 per c via 16-lane shuffles.
__device__ __forceinline__ void stats(Smem& sm, const float* __restrict__ bu,
                                      const float* __restrict__ ba, int tid) {
    for (int q = tid; q < 512; q += 256) {
        int c = q >> 4, p = q & 15, qi = c * 20 + p;
        float s2 = 0.f;
#pragma unroll
        for (int gg = 0; gg < 8; gg++) s2 += sm.WS[gg * 548 + c * 17 + p];
        float rs = sm.RS[c];
        float inv = __fdividef(1.0f, rs + EPSF);
        float mu = sm.M1[qi] * inv;
        // sigma^2 = S2/(rs+eps) - mu^2 * (2 - rs/(rs+eps)) + eps
        float sig = fmaf(-mu * mu, 2.0f - rs * inv, s2 * inv) + EPSF;
        float i2s = __fdividef(0.5f, sig);
        sm.M1[qi] = mu;  // in place: S1 -> mu
        sm.M2[qi] = i2s;
        sm.BB[qi] = -2.0f * i2s * mu;
        // 16-lane reductions (lanes sharing c): 0.5*log(sig) and i2s*mu^2
        float hl = 0.5f * __logf(sig);
        float cc = i2s * mu * mu;
#pragma unroll
        for (int o = 1; o < 16; o <<= 1) {
            hl += __shfl_xor_sync(0xffffffffu, hl, o);
            cc += __shfl_xor_sync(0xffffffffu, cc, o);
        }
        if (p == 0) { sm.SH[c] = hl; sm.CC[c] = cc; }
    }
    __syncthreads();
    if (tid < 32) {
        int c = tid;
        float sumh = sm.SH[c];
        float cost = (16.0f * bu[c] + sumh) * sm.RS[c];
        float logit = LAMBDAF * (ba[c] - cost);
        float ao = __fdividef(1.0f, 1.0f + __expf(-logit));
        sm.AO[c] = ao;
        sm.Lc[c] = __logf(ao + EPSF) - sumh - sm.CC[c];  // C folded in
    }
    __syncthreads();
}

__global__ __launch_bounds__(256, 2) void convcaps_kernel(
    const float* __restrict__ x, const float* __restrict__ a,
    const float* __restrict__ bu, const float* __restrict__ ba,
    const int* __restrict__ itp, float* __restrict__ out) {
    __shared__ Smem sm;
    int tid = threadIdx.x, lane = tid & 31, g = tid >> 5;
    int pid = blockIdx.x;
    int b = pid / 196;
    int rem = pid - b * 196;
    int oy = rem / 14;
    int ox = rem - oy * 14;

    // Patch gather (float4-vectorized): n = (ki*3+kj)*16 + bc
    for (int q = tid; q < 576; q += 256) {
        int n = q >> 2, f = q & 3;
        int bc = n & 15, kk = n >> 4;
        int ki = kk / 3, kj = kk - ki * 3;
        const float4* src = reinterpret_cast<const float4*>(
            x + (((size_t)(b * 16 + oy + ki) * 16 + (ox + kj)) * 16 + bc) * 16);
        reinterpret_cast<float4*>(sm.pose)[q] = __ldg(src + f);
    }
    for (int n = tid; n < NCAP; n += 256) {
        int bc = n & 15, kk = n >> 4;
        int ki = kk / 3, kj = kk - ki * 3;
        sm.a[n] = a[((size_t)(b * 16 + oy + ki) * 16 + (ox + kj)) * 16 + bc];
    }
    __syncthreads();

    int iters = 2;
    if (itp) {
        int iv = __ldg(itp);
        if (iv >= 1 && iv <= 64) {
            iters = iv;
        } else {
            float f = __int_as_float(iv);  // guard against float-encoded scalar
            if (f >= 1.0f && f <= 64.0f) iters = (int)f;
        }
    }

    // iteration 0: uniform responsibilities
    vote_pass0(sm, lane, g, tid);
    stats(sm, bu, ba, tid);
    // iterations 1..iters-1: fused E-step (of prev iter) + M-accumulation
    for (int it = 1; it < iters; ++it) {
        vote_passE(sm, lane, g, tid);
        stats(sm, bu, ba, tid);
    }

    // outputs: p_out (pid*512 + c*16+p) then a_out (POUT_ELEMS + pid*32 + c)
    float* pout = out + (size_t)pid * 512;
    for (int q = tid; q < 512; q += 256) {
        int c = q >> 4, p = q & 15;
        pout[q] = sm.M1[c * 20 + p];
    }
    if (tid < 32) out[POUT_ELEMS + pid * 32 + tid] = sm.AO[tid];
}

extern "C" void kernel_launch(void* const* d_in, const int* in_sizes, int n_in,
                              void* d_out, int out_size) {
    const float* x = (const float*)d_in[0];
    const float* a = (const float*)d_in[1];
    const float* w = (const float*)d_in[2];
    const float* bu = (const float*)d_in[3];
    const float* ba = (const float*)d_in[4];
    const int* itp = (n_in >= 6) ? (const int*)d_in[5] : nullptr;
    convert_w_kernel<<<(WHALF_ELEMS / 8 + 255) / 256, 256>>>(w);
    convcaps_kernel<<<NPOS, 256>>>(x, a, bu, ba, itp, (float*)d_out);
}